// round 1
// baseline (speedup 1.0000x reference)
#include <cuda_runtime.h>

#define NN 50000
#define EE 300000
#define TT 3
#define CC 2
#define HIDD 64

// Scratch (no allocation allowed): ping-pong H buffers, X0, inter-block X, filters.
__device__ __align__(256) float g_H0[CC * NN * HIDD];
__device__ __align__(256) float g_H1[CC * NN * HIDD];
__device__ __align__(256) float g_X0[CC * NN * HIDD];
__device__ __align__(256) float g_Xmid[NN * HIDD];
__device__ float g_filt[2][2][CC][TT];   // [fastgtn_block][layer][channel][etype]

// ---------------------------------------------------------------------------
// Softmax of the tiny mixing weights: layerW[b] has shape [NL=2, C=2, T=3].
__global__ void filt_kernel(const float* __restrict__ lw0,
                            const float* __restrict__ lw1) {
    int t = threadIdx.x;
    if (t >= 8) return;
    int b = t >> 2, l = (t >> 1) & 1, c = t & 1;
    const float* lw = (b ? lw1 : lw0) + (l * CC + c) * TT;
    float a0 = lw[0], a1 = lw[1], a2 = lw[2];
    float m = fmaxf(a0, fmaxf(a1, a2));
    float e0 = __expf(a0 - m), e1 = __expf(a1 - m), e2 = __expf(a2 - m);
    float s = 1.0f / (e0 + e1 + e2);
    g_filt[b][l][c][0] = e0 * s;
    g_filt[b][l][c][1] = e1 * s;
    g_filt[b][l][c][2] = e2 * s;
}

// ---------------------------------------------------------------------------
// H[c] = Xin @ Ws[c]   (also writes X0 copy).  Xin: [N,64], Ws: [C,64,64].
// block: dim3(64,4) -> 4 rows x 64 cols. grid = N/4.
__global__ void gemm_proj_kernel(const float* __restrict__ Xparam,
                                 const float* __restrict__ Ws, int blk) {
    const float* Xin = (blk == 0) ? Xparam : g_Xmid;
    __shared__ float sW[64 * 64];
    __shared__ float sX[4][64];
    int tx = threadIdx.x, ty = threadIdx.y;
    int tid = ty * 64 + tx;
    int n = blockIdx.x * 4 + ty;
    sX[ty][tx] = Xin[(size_t)n * 64 + tx];
#pragma unroll
    for (int c = 0; c < CC; c++) {
        __syncthreads();
#pragma unroll
        for (int i = 0; i < 16; i++)
            sW[tid + i * 256] = Ws[c * 4096 + tid + i * 256];
        __syncthreads();
        float acc = 0.0f;
#pragma unroll
        for (int k = 0; k < 64; k++)
            acc = fmaf(sX[ty][k], sW[k * 64 + tx], acc);
        size_t o = ((size_t)c * NN + n) * 64 + tx;
        g_H0[o] = acc;
        g_X0[o] = acc;
    }
}

// ---------------------------------------------------------------------------
// Zero a ping-pong buffer (float4 stores). count = C*N*64/4 = 1.6M float4.
__global__ void zero_kernel(int buf) {
    size_t i = (size_t)blockIdx.x * blockDim.x + threadIdx.x;
    float4* p = (float4*)(buf ? g_H1 : g_H0);
    p[i] = make_float4(0.f, 0.f, 0.f, 0.f);
}

// ---------------------------------------------------------------------------
// Mixed-adjacency SpMM:  dst[c] += sum_e val[e]*filt[c,type(e)] * src[c][col[e]]
// Thread mapping: 32 lanes per edge; lane = (channel<<4) | chunk, chunk = float4
// index within the 64-float row.  Edge metadata loads are warp-uniform.
__global__ void spmm_kernel(const int* __restrict__ ei0, const int* __restrict__ ei1,
                            const int* __restrict__ ei2,
                            const float* __restrict__ ev0, const float* __restrict__ ev1,
                            const float* __restrict__ ev2,
                            int blk, int layer, int srcbuf) {
    unsigned i = blockIdx.x * blockDim.x + threadIdx.x;
    unsigned e = i >> 5;
    unsigned r = i & 31u;
    int c = (int)(r >> 4);
    int chunk = (int)(r & 15u);

    const int* ei;
    const float* ev;
    int j;
    unsigned local;
    if (e < EE)            { ei = ei0; ev = ev0; j = 0; local = e; }
    else if (e < 2u * EE)  { ei = ei1; ev = ev1; j = 1; local = e - EE; }
    else                   { ei = ei2; ev = ev2; j = 2; local = e - 2u * EE; }

    int row = __ldg(ei + local);
    int col = __ldg(ei + EE + local);
    float coef = __ldg(ev + local) * g_filt[blk][layer][c][j];

    const float* src = srcbuf ? g_H1 : g_H0;
    float* dstb = srcbuf ? g_H0 : g_H1;

    const float4* sp = (const float4*)(src + ((size_t)c * NN + col) * 64) + chunk;
    float4 v = __ldg(sp);
    float* dp = dstb + ((size_t)c * NN + row) * 64 + chunk * 4;
    asm volatile("red.global.add.v4.f32 [%0], {%1, %2, %3, %4};"
                 :: "l"(dp), "f"(v.x * coef), "f"(v.y * coef),
                    "f"(v.z * coef), "f"(v.w * coef)
                 : "memory");
}

// ---------------------------------------------------------------------------
// Teleport mix + reshape [C,N,64]->[N,128] + Linear(128->64) + ReLU.
// block: dim3(64,4). H after NL layers is in g_H0.
__global__ void mix_lin_kernel(const float* __restrict__ linW,
                               const float* __restrict__ linb,
                               float* __restrict__ outp, int blk) {
    __shared__ float sW[128 * 64];
    __shared__ float sb[64];
    __shared__ float shm[4][128];
    int tx = threadIdx.x, ty = threadIdx.y;
    int tid = ty * 64 + tx;
#pragma unroll
    for (int i = 0; i < 32; i++)
        sW[tid + i * 256] = linW[tid + i * 256];
    if (tid < 64) sb[tid] = linb[tid];
    int n = blockIdx.x * 4 + ty;
#pragma unroll
    for (int c = 0; c < CC; c++) {
        size_t o = ((size_t)c * NN + n) * 64 + tx;
        float x0 = g_X0[o];
        float h  = g_H0[o];
        float t = 0.5f * x0 + 0.5f * h;      // BETA = 0.5
        t = fmaxf(t, 0.0f);
        shm[ty][c * 64 + tx] = 0.8f * t + 0.2f * x0;  // TP = 0.8
    }
    __syncthreads();
    float acc = sb[tx];
#pragma unroll
    for (int k = 0; k < 128; k++)
        acc = fmaf(shm[ty][k], sW[k * 64 + tx], acc);
    acc = fmaxf(acc, 0.0f);
    float* op = (blk == 0) ? g_Xmid : outp;
    op[(size_t)n * 64 + tx] = acc;
}

// ---------------------------------------------------------------------------
extern "C" void kernel_launch(void* const* d_in, const int* in_sizes, int n_in,
                              void* d_out, int out_size) {
    const float* X     = (const float*)d_in[0];
    const float* ev0   = (const float*)d_in[1];
    const float* ev1   = (const float*)d_in[2];
    const float* ev2   = (const float*)d_in[3];
    const float* Ws0   = (const float*)d_in[4];
    const float* Ws1   = (const float*)d_in[5];
    const float* lw0   = (const float*)d_in[6];
    const float* lw1   = (const float*)d_in[7];
    const float* linW0 = (const float*)d_in[8];
    const float* linb0 = (const float*)d_in[9];
    const float* linW1 = (const float*)d_in[10];
    const float* linb1 = (const float*)d_in[11];
    const int* ei0     = (const int*)d_in[12];
    const int* ei1     = (const int*)d_in[13];
    const int* ei2     = (const int*)d_in[14];
    float* out = (float*)d_out;

    filt_kernel<<<1, 32>>>(lw0, lw1);

    const int spmm_grid = (3 * EE * 32) / 256;   // 112500, exact
    const int zero_grid = (CC * NN * 64 / 4) / 256;  // 6250, exact
    dim3 tb(64, 4);

    for (int blk = 0; blk < 2; blk++) {
        gemm_proj_kernel<<<NN / 4, tb>>>(X, blk ? Ws1 : Ws0, blk);
        // layer 0: H0 -> H1
        zero_kernel<<<zero_grid, 256>>>(1);
        spmm_kernel<<<spmm_grid, 256>>>(ei0, ei1, ei2, ev0, ev1, ev2, blk, 0, 0);
        // layer 1: H1 -> H0
        zero_kernel<<<zero_grid, 256>>>(0);
        spmm_kernel<<<spmm_grid, 256>>>(ei0, ei1, ei2, ev0, ev1, ev2, blk, 1, 1);
        mix_lin_kernel<<<NN / 4, tb>>>(blk ? linW1 : linW0, blk ? linb1 : linb0, out, blk);
    }
}

// round 2
// speedup vs baseline: 1.4984x; 1.4984x over previous
#include <cuda_runtime.h>

#define NN 50000
#define EE 300000
#define ETOT (3 * EE)
#define TT 3
#define CC 2
#define HIDD 64
#define NBLK ((NN + 255) / 256)   // 196 scan blocks

// Scratch (no allocation allowed).
__device__ __align__(256) float g_H0[CC * NN * HIDD];
__device__ __align__(256) float g_H1[CC * NN * HIDD];
__device__ __align__(256) float g_X0[CC * NN * HIDD];
__device__ __align__(256) float g_Xmid[NN * HIDD];
__device__ float g_filt[2][2][CC][TT];

// CSR scratch
__device__ int g_cnt[NN];
__device__ int g_off[NN + 1];
__device__ int g_cur[NN];
__device__ int g_bsum[256];
__device__ int g_bscan[256];
__device__ __align__(256) uint2 g_csr[ETOT];   // {col | (etype<<16), val bits}

// ---------------------------------------------------------------------------
__global__ void filt_kernel(const float* __restrict__ lw0,
                            const float* __restrict__ lw1) {
    int t = threadIdx.x;
    if (t >= 8) return;
    int b = t >> 2, l = (t >> 1) & 1, c = t & 1;
    const float* lw = (b ? lw1 : lw0) + (l * CC + c) * TT;
    float a0 = lw[0], a1 = lw[1], a2 = lw[2];
    float m = fmaxf(a0, fmaxf(a1, a2));
    float e0 = __expf(a0 - m), e1 = __expf(a1 - m), e2 = __expf(a2 - m);
    float s = 1.0f / (e0 + e1 + e2);
    g_filt[b][l][c][0] = e0 * s;
    g_filt[b][l][c][1] = e1 * s;
    g_filt[b][l][c][2] = e2 * s;
}

// ---------------------------------------------------------------------------
// CSR build: zero counts -> histogram -> 2-level exclusive scan -> scatter.
__global__ void zero_cnt_kernel() {
    int i = blockIdx.x * blockDim.x + threadIdx.x;
    if (i < NN) g_cnt[i] = 0;
}

__device__ __forceinline__ void pick_edge(unsigned e,
                                          const int* ei0, const int* ei1, const int* ei2,
                                          const float* ev0, const float* ev1, const float* ev2,
                                          const int** ei, const float** ev,
                                          int* j, unsigned* local) {
    if (e < EE)           { *ei = ei0; *ev = ev0; *j = 0; *local = e; }
    else if (e < 2u * EE) { *ei = ei1; *ev = ev1; *j = 1; *local = e - EE; }
    else                  { *ei = ei2; *ev = ev2; *j = 2; *local = e - 2u * EE; }
}

__global__ void hist_kernel(const int* __restrict__ ei0, const int* __restrict__ ei1,
                            const int* __restrict__ ei2) {
    unsigned e = blockIdx.x * blockDim.x + threadIdx.x;
    if (e >= ETOT) return;
    const int* ei; const float* ev; int j; unsigned local;
    pick_edge(e, ei0, ei1, ei2, nullptr, nullptr, nullptr, &ei, &ev, &j, &local);
    atomicAdd(&g_cnt[__ldg(ei + local)], 1);
}

__global__ void scanA_kernel() {
    __shared__ int s[256];
    int i = blockIdx.x * 256 + threadIdx.x;
    int v = (i < NN) ? g_cnt[i] : 0;
    s[threadIdx.x] = v;
    __syncthreads();
#pragma unroll
    for (int o = 128; o > 0; o >>= 1) {
        if (threadIdx.x < o) s[threadIdx.x] += s[threadIdx.x + o];
        __syncthreads();
    }
    if (threadIdx.x == 0) g_bsum[blockIdx.x] = s[0];
}

__global__ void scanB_kernel() {
    __shared__ int s[256];
    int t = threadIdx.x;
    int v = (t < NBLK) ? g_bsum[t] : 0;
    s[t] = v;
    __syncthreads();
#pragma unroll
    for (int o = 1; o < 256; o <<= 1) {
        int x = (t >= o) ? s[t - o] : 0;
        __syncthreads();
        s[t] += x;
        __syncthreads();
    }
    g_bscan[t] = s[t] - v;   // exclusive
    if (t == 0) g_off[NN] = ETOT;
}

__global__ void scanC_kernel() {
    __shared__ int s[256];
    int t = threadIdx.x;
    int i = blockIdx.x * 256 + t;
    int v = (i < NN) ? g_cnt[i] : 0;
    s[t] = v;
    __syncthreads();
#pragma unroll
    for (int o = 1; o < 256; o <<= 1) {
        int x = (t >= o) ? s[t - o] : 0;
        __syncthreads();
        s[t] += x;
        __syncthreads();
    }
    if (i < NN) {
        int excl = s[t] - v + g_bscan[blockIdx.x];
        g_off[i] = excl;
        g_cur[i] = excl;
    }
}

__global__ void scatter_kernel(const int* __restrict__ ei0, const int* __restrict__ ei1,
                               const int* __restrict__ ei2,
                               const float* __restrict__ ev0, const float* __restrict__ ev1,
                               const float* __restrict__ ev2) {
    unsigned e = blockIdx.x * blockDim.x + threadIdx.x;
    if (e >= ETOT) return;
    const int* ei; const float* ev; int j; unsigned local;
    pick_edge(e, ei0, ei1, ei2, ev0, ev1, ev2, &ei, &ev, &j, &local);
    int row = __ldg(ei + local);
    int col = __ldg(ei + EE + local);
    float val = __ldg(ev + local);
    int pos = atomicAdd(&g_cur[row], 1);
    g_csr[pos] = make_uint2((unsigned)col | ((unsigned)j << 16), __float_as_uint(val));
}

// ---------------------------------------------------------------------------
// H[c] = Xin @ Ws[c]  (also writes X0 copy).  16 rows per block.
__global__ void gemm_proj_kernel(const float* __restrict__ Xparam,
                                 const float* __restrict__ Ws, int blk) {
    const float* Xin = (blk == 0) ? Xparam : g_Xmid;
    __shared__ float sW[64 * 64];
    __shared__ float sX[16][64];
    int tx = threadIdx.x, ty = threadIdx.y;
    int tid = ty * 64 + tx;
    int n = blockIdx.x * 16 + ty;
    sX[ty][tx] = Xin[(size_t)n * 64 + tx];
#pragma unroll
    for (int c = 0; c < CC; c++) {
        __syncthreads();
#pragma unroll
        for (int i = 0; i < 4; i++)
            sW[tid + i * 1024] = Ws[c * 4096 + tid + i * 1024];
        __syncthreads();
        float acc = 0.0f;
#pragma unroll
        for (int k = 0; k < 64; k++)
            acc = fmaf(sX[ty][k], sW[k * 64 + tx], acc);
        size_t o = ((size_t)c * NN + n) * 64 + tx;
        g_H0[o] = acc;
        g_X0[o] = acc;
    }
}

// ---------------------------------------------------------------------------
// CSR SpMM: one warp per destination row; lanes split as 2 channels x 16 chunks.
// acc in registers, single STG.128 per lane at the end (no atomics, no zeroing).
__global__ void spmm_csr_kernel(int blk, int layer, int srcbuf) {
    unsigned gw = (blockIdx.x * blockDim.x + threadIdx.x) >> 5;
    if (gw >= NN) return;
    int lane = threadIdx.x & 31;
    int c = lane >> 4;
    int chunk = lane & 15;

    float f0 = g_filt[blk][layer][c][0];
    float f1 = g_filt[blk][layer][c][1];
    float f2 = g_filt[blk][layer][c][2];

    const float* src = srcbuf ? g_H1 : g_H0;
    float* dst = srcbuf ? g_H0 : g_H1;
    const float4* srcb = (const float4*)(src + (size_t)c * NN * 64) ;

    int s = __ldg(&g_off[gw]);
    int e = __ldg(&g_off[gw + 1]);

    float4 acc = make_float4(0.f, 0.f, 0.f, 0.f);
#pragma unroll 4
    for (int i = s; i < e; i++) {
        uint2 ent = __ldg(&g_csr[i]);
        int col = (int)(ent.x & 0xFFFFu);
        int et = (int)(ent.x >> 16);
        float coef = __uint_as_float(ent.y) * (et == 0 ? f0 : (et == 1 ? f1 : f2));
        float4 v = __ldg(srcb + (size_t)col * 16 + chunk);
        acc.x = fmaf(coef, v.x, acc.x);
        acc.y = fmaf(coef, v.y, acc.y);
        acc.z = fmaf(coef, v.z, acc.z);
        acc.w = fmaf(coef, v.w, acc.w);
    }
    *((float4*)(dst + ((size_t)c * NN + gw) * 64) + chunk) = acc;
}

// ---------------------------------------------------------------------------
// Teleport mix + reshape + Linear(128->64) + ReLU.  16 rows per block.
__global__ void mix_lin_kernel(const float* __restrict__ linW,
                               const float* __restrict__ linb,
                               float* __restrict__ outp, int blk) {
    __shared__ float sW[128 * 64];
    __shared__ float sb[64];
    __shared__ float shm[16][128];
    int tx = threadIdx.x, ty = threadIdx.y;
    int tid = ty * 64 + tx;
#pragma unroll
    for (int i = 0; i < 8; i++)
        sW[tid + i * 1024] = linW[tid + i * 1024];
    if (tid < 64) sb[tid] = linb[tid];
    int n = blockIdx.x * 16 + ty;
#pragma unroll
    for (int c = 0; c < CC; c++) {
        size_t o = ((size_t)c * NN + n) * 64 + tx;
        float x0 = g_X0[o];
        float h = g_H0[o];
        float t = 0.5f * x0 + 0.5f * h;            // BETA = 0.5
        t = fmaxf(t, 0.0f);
        shm[ty][c * 64 + tx] = 0.8f * t + 0.2f * x0;  // TP = 0.8
    }
    __syncthreads();
    float acc = sb[tx];
#pragma unroll
    for (int k = 0; k < 128; k++)
        acc = fmaf(shm[ty][k], sW[k * 64 + tx], acc);
    acc = fmaxf(acc, 0.0f);
    float* op = (blk == 0) ? g_Xmid : outp;
    op[(size_t)n * 64 + tx] = acc;
}

// ---------------------------------------------------------------------------
extern "C" void kernel_launch(void* const* d_in, const int* in_sizes, int n_in,
                              void* d_out, int out_size) {
    const float* X     = (const float*)d_in[0];
    const float* ev0   = (const float*)d_in[1];
    const float* ev1   = (const float*)d_in[2];
    const float* ev2   = (const float*)d_in[3];
    const float* Ws0   = (const float*)d_in[4];
    const float* Ws1   = (const float*)d_in[5];
    const float* lw0   = (const float*)d_in[6];
    const float* lw1   = (const float*)d_in[7];
    const float* linW0 = (const float*)d_in[8];
    const float* linb0 = (const float*)d_in[9];
    const float* linW1 = (const float*)d_in[10];
    const float* linb1 = (const float*)d_in[11];
    const int* ei0     = (const int*)d_in[12];
    const int* ei1     = (const int*)d_in[13];
    const int* ei2     = (const int*)d_in[14];
    float* out = (float*)d_out;

    filt_kernel<<<1, 32>>>(lw0, lw1);

    // CSR build (reused by all 4 SpMMs)
    const int egrid = (ETOT + 255) / 256;
    zero_cnt_kernel<<<(NN + 255) / 256, 256>>>();
    hist_kernel<<<egrid, 256>>>(ei0, ei1, ei2);
    scanA_kernel<<<NBLK, 256>>>();
    scanB_kernel<<<1, 256>>>();
    scanC_kernel<<<NBLK, 256>>>();
    scatter_kernel<<<egrid, 256>>>(ei0, ei1, ei2, ev0, ev1, ev2);

    const int spmm_grid = (NN * 32 + 255) / 256;   // 1 warp per row
    dim3 tb(64, 16);

    for (int blk = 0; blk < 2; blk++) {
        gemm_proj_kernel<<<NN / 16, tb>>>(X, blk ? Ws1 : Ws0, blk);
        spmm_csr_kernel<<<spmm_grid, 256>>>(blk, 0, 0);   // H0 -> H1
        spmm_csr_kernel<<<spmm_grid, 256>>>(blk, 1, 1);   // H1 -> H0
        mix_lin_kernel<<<NN / 16, tb>>>(blk ? linW1 : linW0, blk ? linb1 : linb0, out, blk);
    }
}